// round 3
// baseline (speedup 1.0000x reference)
#include <cuda_runtime.h>
#include <math.h>

// Problem constants
#define CB   4          // batch
#define CTT  4160       // total tokens = W + F
#define CF   4096       // frames
#define CWN  64         // windows (word tokens)
#define CE   256        // embed dim
#define CH   4          // heads
#define CD   64         // head dim
#define LS   15         // local window
#define HALO 7
#define QSCALE 0.125f   // 64^-0.5

// Scratch (device globals: allocation-free)
__device__ float g_qkv [CB * CTT * 768];   // (b,t, [Q|K|V] x 256)
__device__ float g_expa[CB * CF  * CE];    // (b,f,e)
__device__ float g_attn[CB * CTT * CE];    // (b,t,e) pre-output-projection

// ---------------------------------------------------------------------------
// Tiled fp32 SGEMM core: C[M x N] = A[M x K] @ B[K x N] + bias
// BM=128, BN=64, BK=16, 256 threads, 8x4 per-thread tile.
// Requires M%128==0, N%64==0, K%16==0 (all shapes here satisfy this).
// ---------------------------------------------------------------------------
template <int N, int K>
__device__ __forceinline__ void sgemm_core(const float* __restrict__ A,
                                           const float* __restrict__ B,
                                           const float* __restrict__ bias,
                                           float* __restrict__ C)
{
    __shared__ float As[16][128];
    __shared__ float Bs[16][64];

    const int tid = threadIdx.x;
    const int m0  = blockIdx.y * 128;
    const int n0  = blockIdx.x * 64;
    const int tx  = tid & 15;   // -> n (4 cols each)
    const int ty  = tid >> 4;   // -> m (8 rows each)

    const int arow = tid >> 1;          // 0..127
    const int acol = (tid & 1) * 8;     // 0 or 8
    const int brow = tid >> 4;          // 0..15
    const int bcol = (tid & 15) * 4;    // 0..60

    float acc[8][4] = {};

    for (int k0 = 0; k0 < K; k0 += 16) {
        const float* ap = A + (size_t)(m0 + arow) * K + k0 + acol;
        float4 a0 = *(const float4*)(ap);
        float4 a1 = *(const float4*)(ap + 4);
        As[acol + 0][arow] = a0.x; As[acol + 1][arow] = a0.y;
        As[acol + 2][arow] = a0.z; As[acol + 3][arow] = a0.w;
        As[acol + 4][arow] = a1.x; As[acol + 5][arow] = a1.y;
        As[acol + 6][arow] = a1.z; As[acol + 7][arow] = a1.w;

        *(float4*)&Bs[brow][bcol] =
            *(const float4*)(B + (size_t)(k0 + brow) * N + n0 + bcol);

        __syncthreads();

        #pragma unroll
        for (int kk = 0; kk < 16; kk++) {
            float ra[8], rb[4];
            *(float4*)(ra    ) = *(const float4*)&As[kk][ty * 8];
            *(float4*)(ra + 4) = *(const float4*)&As[kk][ty * 8 + 4];
            *(float4*)(rb    ) = *(const float4*)&Bs[kk][tx * 4];
            #pragma unroll
            for (int i = 0; i < 8; i++)
                #pragma unroll
                for (int j = 0; j < 4; j++)
                    acc[i][j] = fmaf(ra[i], rb[j], acc[i][j]);
        }
        __syncthreads();
    }

    float4 bb = *(const float4*)(bias + n0 + tx * 4);
    #pragma unroll
    for (int i = 0; i < 8; i++) {
        float4 o;
        o.x = acc[i][0] + bb.x;
        o.y = acc[i][1] + bb.y;
        o.z = acc[i][2] + bb.z;
        o.w = acc[i][3] + bb.w;
        *(float4*)(C + (size_t)(m0 + ty * 8 + i) * N + n0 + tx * 4) = o;
    }
}

__global__ __launch_bounds__(256)
void k_qkv(const float* __restrict__ x, const float* __restrict__ Wq,
           const float* __restrict__ bq)
{
    sgemm_core<768, 256>(x, Wq, bq, g_qkv);
}

__global__ __launch_bounds__(256)
void k_out(const float* __restrict__ Wo, const float* __restrict__ bo,
           float* __restrict__ out)
{
    sgemm_core<256, 256>(g_attn, Wo, bo, out);
}

// ---------------------------------------------------------------------------
// expa[b,f,e] = sum_w wm[b,w,f] * x[b,w,e]        (K = 64 windows)
// Block: 64 f x 64 e tile. Grid: (E/64, F/64, B)
// ---------------------------------------------------------------------------
__global__ __launch_bounds__(256)
void k_expa(const float* __restrict__ wm, const float* __restrict__ x)
{
    __shared__ float As[64][64];  // [w][f]
    __shared__ float Bs[64][64];  // [w][e]

    const int b  = blockIdx.z;
    const int f0 = blockIdx.y * 64;
    const int e0 = blockIdx.x * 64;
    const int tid = threadIdx.x;

    for (int i = tid; i < 64 * 16; i += 256) {
        int w  = i >> 4;
        int c4 = (i & 15) * 4;
        *(float4*)&As[w][c4] =
            *(const float4*)(wm + (size_t)(b * CWN + w) * CF + f0 + c4);
        *(float4*)&Bs[w][c4] =
            *(const float4*)(x + (size_t)(b * CTT + w) * CE + e0 + c4);
    }
    __syncthreads();

    const int tx = tid & 15, ty = tid >> 4;
    float acc[4][4] = {};
    #pragma unroll 8
    for (int w = 0; w < 64; w++) {
        float ra[4], rb[4];
        *(float4*)ra = *(const float4*)&As[w][ty * 4];
        *(float4*)rb = *(const float4*)&Bs[w][tx * 4];
        #pragma unroll
        for (int i = 0; i < 4; i++)
            #pragma unroll
            for (int j = 0; j < 4; j++)
                acc[i][j] = fmaf(ra[i], rb[j], acc[i][j]);
    }

    #pragma unroll
    for (int i = 0; i < 4; i++) {
        float4 o = { acc[i][0], acc[i][1], acc[i][2], acc[i][3] };
        *(float4*)(g_expa + (size_t)(b * CF + f0 + ty * 4 + i) * CE + e0 + tx * 4) = o;
    }
}

// ---------------------------------------------------------------------------
// Word-token rows pass through unchanged: g_attn[b, t<64, :] = x[b, t<64, :]
// ---------------------------------------------------------------------------
__global__ void k_copy(const float* __restrict__ x)
{
    int i = blockIdx.x * 256 + threadIdx.x;     // 0 .. 65535
    int b = i >> 14;                            // / (64*256)
    int r = i & 16383;
    g_attn[(size_t)b * CTT * CE + r] = x[(size_t)b * CTT * CE + r];
}

// ---------------------------------------------------------------------------
// Attention: one block per (n = b*4+h, chunk c of 64 frames). 256 thr = 8 warps,
// each warp owns 8 frames. K/V halo (78 rows) zero-filled => OOB scores are
// exactly 0 and OOB V contributes 0, matching the reference's zero padding.
// Chunk softmax over the 64 word-token scores; per-frame softmax over 15 local.
// ---------------------------------------------------------------------------
__global__ __launch_bounds__(256)
void k_attn()
{
    __shared__ float sK[78][64];
    __shared__ float sV[78][64];
    __shared__ float s0[64];

    const int n = blockIdx.y, c = blockIdx.x;
    const int b = n >> 2, h = n & 3;
    const int tid = threadIdx.x;

    // Load K/V halo tiles, zero-filling out-of-range frames
    for (int i = tid; i < 78 * 16; i += 256) {
        int row = i >> 4;
        int c4  = (i & 15) * 4;
        int gf  = c * 64 - HALO + row;
        float4 kv = {0.f, 0.f, 0.f, 0.f};
        float4 vv = {0.f, 0.f, 0.f, 0.f};
        if (gf >= 0 && gf < CF) {
            const float* p = g_qkv + (size_t)(b * CTT + CWN + gf) * 768 + h * 64 + c4;
            kv = *(const float4*)(p + 256);
            vv = *(const float4*)(p + 512);
        }
        *(float4*)&sK[row][c4] = kv;
        *(float4*)&sV[row][c4] = vv;
    }
    __syncthreads();

    const int warp = tid >> 5, lane = tid & 31;

    float q0[8], q1[8], e0a[8], e1a[8], sc0[8];

    // Phase 1: word-token scores (q . expa), per frame
    #pragma unroll
    for (int fi = 0; fi < 8; fi++) {
        int lf = warp * 8 + fi;
        int f  = c * 64 + lf;
        const float* qp = g_qkv + (size_t)(b * CTT + CWN + f) * 768 + h * 64;
        q0[fi] = qp[lane] * QSCALE;
        q1[fi] = qp[lane + 32] * QSCALE;
        const float* ep = g_expa + (size_t)(b * CF + f) * CE + h * 64;
        e0a[fi] = ep[lane];
        e1a[fi] = ep[lane + 32];
        float p = q0[fi] * e0a[fi] + q1[fi] * e1a[fi];
        #pragma unroll
        for (int off = 16; off; off >>= 1)
            p += __shfl_xor_sync(0xffffffffu, p, off);
        sc0[fi] = p;
        if (lane == 0) s0[lf] = p;
    }
    __syncthreads();

    // Chunk softmax normalization over the 64 word-token scores (per warp, redundant)
    float v0 = s0[lane], v1 = s0[lane + 32];
    float M = fmaxf(v0, v1);
    #pragma unroll
    for (int off = 16; off; off >>= 1)
        M = fmaxf(M, __shfl_xor_sync(0xffffffffu, M, off));
    float S = expf(v0 - M) + expf(v1 - M);
    #pragma unroll
    for (int off = 16; off; off >>= 1)
        S += __shfl_xor_sync(0xffffffffu, S, off);
    const float Sinv = 1.f / S;

    // Phase 2: local window scores, softmax, weighted sum
    #pragma unroll
    for (int fi = 0; fi < 8; fi++) {
        int lf = warp * 8 + fi;
        int f  = c * 64 + lf;

        float p[LS];
        #pragma unroll
        for (int j = 0; j < LS; j++) {
            int r = lf + j;   // halo-offset row: global frame f - 7 + j
            p[j] = q0[fi] * sK[r][lane] + q1[fi] * sK[r][lane + 32];
        }
        #pragma unroll
        for (int j = 0; j < LS; j++) {
            #pragma unroll
            for (int off = 16; off; off >>= 1)
                p[j] += __shfl_xor_sync(0xffffffffu, p[j], off);
        }

        float mx = p[0];
        #pragma unroll
        for (int j = 1; j < LS; j++) mx = fmaxf(mx, p[j]);
        float w[LS], s = 0.f;
        #pragma unroll
        for (int j = 0; j < LS; j++) { w[j] = expf(p[j] - mx); s += w[j]; }
        const float inv = 1.f / s;

        const float w0 = expf(sc0[fi] - M) * Sinv;
        float o0 = w0 * e0a[fi];
        float o1 = w0 * e1a[fi];
        #pragma unroll
        for (int j = 0; j < LS; j++) {
            int r = lf + j;
            float wj = w[j] * inv;
            o0 = fmaf(wj, sV[r][lane],      o0);
            o1 = fmaf(wj, sV[r][lane + 32], o1);
        }

        float* op = g_attn + (size_t)(b * CTT + CWN + f) * CE + h * 64;
        op[lane]      = o0;
        op[lane + 32] = o1;
    }
}

// ---------------------------------------------------------------------------
extern "C" void kernel_launch(void* const* d_in, const int* in_sizes, int n_in,
                              void* d_out, int out_size)
{
    const float *x = nullptr, *wm = nullptr, *Wq = nullptr, *bq = nullptr,
                *Wo = nullptr, *bo = nullptr;
    // Sizes are pairwise distinct: resolve inputs by element count.
    for (int i = 0; i < n_in; i++) {
        switch (in_sizes[i]) {
            case 4259840: x  = (const float*)d_in[i]; break;  // (4,4160,256)
            case 1048576: wm = (const float*)d_in[i]; break;  // (4,64,4096)
            case  196608: Wq = (const float*)d_in[i]; break;  // (256,768)
            case     768: bq = (const float*)d_in[i]; break;
            case   65536: Wo = (const float*)d_in[i]; break;  // (256,256)
            case     256: bo = (const float*)d_in[i]; break;
            default: break;
        }
    }

    // 1) qkv = x @ W_qkv + b_qkv   (M=16640, N=768, K=256)
    k_qkv<<<dim3(768 / 64, (CB * CTT) / 128), 256>>>(x, Wq, bq);
    // 2) expa = wm^T @ x_words      (per batch: 4096 x 256, K=64)
    k_expa<<<dim3(CE / 64, CF / 64, CB), 256>>>(wm, x);
    // 3) word-token passthrough rows
    k_copy<<<256, 256>>>(x);
    // 4) local + word-token attention
    k_attn<<<dim3(CF / 64, CB * CH), 256>>>();
    // 5) out = attn @ W_out + b_out (M=16640, N=256, K=256)
    k_out<<<dim3(256 / 64, (CB * CTT) / 128), 256>>>(Wo, bo, (float*)d_out);
}

// round 6
// speedup vs baseline: 1.4769x; 1.4769x over previous
#include <cuda_runtime.h>
#include <stdint.h>
#include <math.h>

// Problem constants
#define CB   4          // batch
#define CTT  4160       // total tokens = W + F
#define CF   4096       // frames
#define CWN  64         // windows (word tokens)
#define CE   256        // embed dim
#define CH   4          // heads
#define CD   64         // head dim
#define LS   15         // local window
#define HALO 7
#define QSCALE 0.125f   // 64^-0.5

// Scratch (device globals: allocation-free)
__device__ float g_qkv [CB * CTT * 768];   // (b,t, [Q|K|V] x 256)
__device__ float g_expa[CB * CF  * CE];    // (b,f,e)
__device__ float g_attn[CB * CTT * CE];    // (b,t,e) pre-output-projection

// ---------------------------------------------------------------------------
// TF32 tensor-core GEMM: C[M x N] = A[M x K] @ B[K x N] + bias
// BM=128, BN=128, BK=32. 256 threads = 8 warps in a 2(m) x 4(n) grid;
// each warp computes a 64x32 tile = 4x4 m16n8k8 mma tiles.
// Inputs converted to tf32 (cvt.rna) during smem staging; fp32 accumulate.
// ---------------------------------------------------------------------------
__device__ __forceinline__ unsigned int f2tf(float x) {
    unsigned int r;
    asm("cvt.rna.tf32.f32 %0, %1;" : "=r"(r) : "f"(x));
    return r;
}

__device__ __forceinline__ void mma_tf32(float* d, const unsigned int* a,
                                         const unsigned int* b) {
    asm volatile(
        "mma.sync.aligned.m16n8k8.row.col.f32.tf32.tf32.f32 "
        "{%0,%1,%2,%3}, {%4,%5,%6,%7}, {%8,%9}, {%0,%1,%2,%3};"
        : "+f"(d[0]), "+f"(d[1]), "+f"(d[2]), "+f"(d[3])
        : "r"(a[0]), "r"(a[1]), "r"(a[2]), "r"(a[3]), "r"(b[0]), "r"(b[1]));
}

template <int N, int K>
__device__ __forceinline__ void tf32_gemm_core(const float* __restrict__ A,
                                               const float* __restrict__ B,
                                               const float* __restrict__ bias,
                                               float* __restrict__ C)
{
    constexpr int BM = 128, BN = 128, BK = 32;
    __shared__ unsigned int As[BK][BM + 8];   // [k][m]
    __shared__ unsigned int Bs[BN][BK + 4];   // [n][k]

    const int tid  = threadIdx.x;
    const int warp = tid >> 5, lane = tid & 31;
    const int wm_  = warp >> 2;        // 0..1  -> m offset *64
    const int wn_  = warp & 3;         // 0..3  -> n offset *32
    const int gid  = lane >> 2;        // 0..7
    const int tg   = lane & 3;         // 0..3
    const int m0   = blockIdx.y * BM;
    const int n0   = blockIdx.x * BN;

    // staging coordinates
    const int a_row = tid & 127;              // A: row within tile
    const int a_kq  = (tid >> 7) * 16;        // A: k-quarter (0 or 16)
    const int b_kk  = tid & 31;               // B: k row
    const int b_ng  = (tid >> 5) * 16;        // B: n group of 16

    float acc[4][4][4] = {};

    for (int k0 = 0; k0 < K; k0 += BK) {
        // stage A tile -> As[k][m] (tf32)
        {
            const float* ap = A + (size_t)(m0 + a_row) * K + k0 + a_kq;
            #pragma unroll
            for (int q = 0; q < 4; q++) {
                float4 v = *(const float4*)(ap + q * 4);
                As[a_kq + q * 4 + 0][a_row] = f2tf(v.x);
                As[a_kq + q * 4 + 1][a_row] = f2tf(v.y);
                As[a_kq + q * 4 + 2][a_row] = f2tf(v.z);
                As[a_kq + q * 4 + 3][a_row] = f2tf(v.w);
            }
        }
        // stage B tile -> Bs[n][k] (tf32)
        {
            const float* bp = B + (size_t)(k0 + b_kk) * N + n0 + b_ng;
            #pragma unroll
            for (int q = 0; q < 4; q++) {
                float4 v = *(const float4*)(bp + q * 4);
                Bs[b_ng + q * 4 + 0][b_kk] = f2tf(v.x);
                Bs[b_ng + q * 4 + 1][b_kk] = f2tf(v.y);
                Bs[b_ng + q * 4 + 2][b_kk] = f2tf(v.z);
                Bs[b_ng + q * 4 + 3][b_kk] = f2tf(v.w);
            }
        }
        __syncthreads();

        #pragma unroll
        for (int ks = 0; ks < 4; ks++) {
            const int kb = ks * 8;
            unsigned int af[4][4], bf[4][2];
            #pragma unroll
            for (int mi = 0; mi < 4; mi++) {
                int mr = wm_ * 64 + mi * 16 + gid;
                af[mi][0] = As[kb + tg    ][mr];
                af[mi][1] = As[kb + tg    ][mr + 8];
                af[mi][2] = As[kb + tg + 4][mr];
                af[mi][3] = As[kb + tg + 4][mr + 8];
            }
            #pragma unroll
            for (int ni = 0; ni < 4; ni++) {
                int nc = wn_ * 32 + ni * 8 + gid;
                bf[ni][0] = Bs[nc][kb + tg];
                bf[ni][1] = Bs[nc][kb + tg + 4];
            }
            #pragma unroll
            for (int mi = 0; mi < 4; mi++)
                #pragma unroll
                for (int ni = 0; ni < 4; ni++)
                    mma_tf32(acc[mi][ni], af[mi], bf[ni]);
        }
        __syncthreads();
    }

    // epilogue: bias add + store
    #pragma unroll
    for (int ni = 0; ni < 4; ni++) {
        int c0 = n0 + wn_ * 32 + ni * 8 + tg * 2;
        float b0v = bias[c0], b1v = bias[c0 + 1];
        #pragma unroll
        for (int mi = 0; mi < 4; mi++) {
            int r0 = m0 + wm_ * 64 + mi * 16 + gid;
            float2 o0 = { acc[mi][ni][0] + b0v, acc[mi][ni][1] + b1v };
            float2 o1 = { acc[mi][ni][2] + b0v, acc[mi][ni][3] + b1v };
            *(float2*)(C + (size_t)r0 * N + c0)       = o0;
            *(float2*)(C + (size_t)(r0 + 8) * N + c0) = o1;
        }
    }
}

__global__ __launch_bounds__(256)
void k_qkv(const float* __restrict__ x, const float* __restrict__ Wq,
           const float* __restrict__ bq)
{
    tf32_gemm_core<768, 256>(x, Wq, bq, g_qkv);
}

__global__ __launch_bounds__(256)
void k_out(const float* __restrict__ Wo, const float* __restrict__ bo,
           float* __restrict__ out)
{
    tf32_gemm_core<256, 256>(g_attn, Wo, bo, out);
}

// ---------------------------------------------------------------------------
// expa[b,f,e] = sum_w wm[b,w,f] * x[b,w,e]        (K = 64 windows, fp32 exact)
// ---------------------------------------------------------------------------
__global__ __launch_bounds__(256)
void k_expa(const float* __restrict__ wm, const float* __restrict__ x)
{
    __shared__ float As[64][64];  // [w][f]
    __shared__ float Bs[64][64];  // [w][e]

    const int b  = blockIdx.z;
    const int f0 = blockIdx.y * 64;
    const int e0 = blockIdx.x * 64;
    const int tid = threadIdx.x;

    for (int i = tid; i < 64 * 16; i += 256) {
        int w  = i >> 4;
        int c4 = (i & 15) * 4;
        *(float4*)&As[w][c4] =
            *(const float4*)(wm + (size_t)(b * CWN + w) * CF + f0 + c4);
        *(float4*)&Bs[w][c4] =
            *(const float4*)(x + (size_t)(b * CTT + w) * CE + e0 + c4);
    }
    __syncthreads();

    const int tx = tid & 15, ty = tid >> 4;
    float acc[4][4] = {};
    #pragma unroll 8
    for (int w = 0; w < 64; w++) {
        float ra[4], rb[4];
        *(float4*)ra = *(const float4*)&As[w][ty * 4];
        *(float4*)rb = *(const float4*)&Bs[w][tx * 4];
        #pragma unroll
        for (int i = 0; i < 4; i++)
            #pragma unroll
            for (int j = 0; j < 4; j++)
                acc[i][j] = fmaf(ra[i], rb[j], acc[i][j]);
    }

    #pragma unroll
    for (int i = 0; i < 4; i++) {
        float4 o = { acc[i][0], acc[i][1], acc[i][2], acc[i][3] };
        *(float4*)(g_expa + (size_t)(b * CF + f0 + ty * 4 + i) * CE + e0 + tx * 4) = o;
    }
}

// ---------------------------------------------------------------------------
// Word-token rows pass through unchanged: g_attn[b, t<64, :] = x[b, t<64, :]
// ---------------------------------------------------------------------------
__global__ void k_copy(const float* __restrict__ x)
{
    int i = blockIdx.x * 256 + threadIdx.x;     // 0 .. 65535
    int b = i >> 14;
    int r = i & 16383;
    g_attn[(size_t)b * CTT * CE + r] = x[(size_t)b * CTT * CE + r];
}

// ---------------------------------------------------------------------------
// Attention: one block per (n = b*4+h, chunk c of 64 frames). 256 thr = 8 warps,
// each warp owns 8 frames. K/V halo (78 rows) zero-filled => OOB scores are
// exactly 0 and OOB V contributes 0, matching the reference's zero padding.
// ---------------------------------------------------------------------------
__global__ __launch_bounds__(256)
void k_attn()
{
    __shared__ float sK[78][64];
    __shared__ float sV[78][64];
    __shared__ float s0[64];

    const int n = blockIdx.y, c = blockIdx.x;
    const int b = n >> 2, h = n & 3;
    const int tid = threadIdx.x;

    for (int i = tid; i < 78 * 16; i += 256) {
        int row = i >> 4;
        int c4  = (i & 15) * 4;
        int gf  = c * 64 - HALO + row;
        float4 kv = {0.f, 0.f, 0.f, 0.f};
        float4 vv = {0.f, 0.f, 0.f, 0.f};
        if (gf >= 0 && gf < CF) {
            const float* p = g_qkv + (size_t)(b * CTT + CWN + gf) * 768 + h * 64 + c4;
            kv = *(const float4*)(p + 256);
            vv = *(const float4*)(p + 512);
        }
        *(float4*)&sK[row][c4] = kv;
        *(float4*)&sV[row][c4] = vv;
    }
    __syncthreads();

    const int warp = tid >> 5, lane = tid & 31;

    float q0[8], q1[8], e0a[8], e1a[8], sc0[8];

    #pragma unroll
    for (int fi = 0; fi < 8; fi++) {
        int lf = warp * 8 + fi;
        int f  = c * 64 + lf;
        const float* qp = g_qkv + (size_t)(b * CTT + CWN + f) * 768 + h * 64;
        q0[fi] = qp[lane] * QSCALE;
        q1[fi] = qp[lane + 32] * QSCALE;
        const float* ep = g_expa + (size_t)(b * CF + f) * CE + h * 64;
        e0a[fi] = ep[lane];
        e1a[fi] = ep[lane + 32];
        float p = q0[fi] * e0a[fi] + q1[fi] * e1a[fi];
        #pragma unroll
        for (int off = 16; off; off >>= 1)
            p += __shfl_xor_sync(0xffffffffu, p, off);
        sc0[fi] = p;
        if (lane == 0) s0[lf] = p;
    }
    __syncthreads();

    float v0 = s0[lane], v1 = s0[lane + 32];
    float M = fmaxf(v0, v1);
    #pragma unroll
    for (int off = 16; off; off >>= 1)
        M = fmaxf(M, __shfl_xor_sync(0xffffffffu, M, off));
    float S = expf(v0 - M) + expf(v1 - M);
    #pragma unroll
    for (int off = 16; off; off >>= 1)
        S += __shfl_xor_sync(0xffffffffu, S, off);
    const float Sinv = 1.f / S;

    #pragma unroll
    for (int fi = 0; fi < 8; fi++) {
        int lf = warp * 8 + fi;
        int f  = c * 64 + lf;

        float p[LS];
        #pragma unroll
        for (int j = 0; j < LS; j++) {
            int r = lf + j;
            p[j] = q0[fi] * sK[r][lane] + q1[fi] * sK[r][lane + 32];
        }
        #pragma unroll
        for (int j = 0; j < LS; j++) {
            #pragma unroll
            for (int off = 16; off; off >>= 1)
                p[j] += __shfl_xor_sync(0xffffffffu, p[j], off);
        }

        float mx = p[0];
        #pragma unroll
        for (int j = 1; j < LS; j++) mx = fmaxf(mx, p[j]);
        float w[LS], s = 0.f;
        #pragma unroll
        for (int j = 0; j < LS; j++) { w[j] = expf(p[j] - mx); s += w[j]; }
        const float inv = 1.f / s;

        const float w0 = expf(sc0[fi] - M) * Sinv;
        float o0 = w0 * e0a[fi];
        float o1 = w0 * e1a[fi];
        #pragma unroll
        for (int j = 0; j < LS; j++) {
            int r = lf + j;
            float wj = w[j] * inv;
            o0 = fmaf(wj, sV[r][lane],      o0);
            o1 = fmaf(wj, sV[r][lane + 32], o1);
        }

        float* op = g_attn + (size_t)(b * CTT + CWN + f) * CE + h * 64;
        op[lane]      = o0;
        op[lane + 32] = o1;
    }
}

// ---------------------------------------------------------------------------
extern "C" void kernel_launch(void* const* d_in, const int* in_sizes, int n_in,
                              void* d_out, int out_size)
{
    const float *x = nullptr, *wm = nullptr, *Wq = nullptr, *bq = nullptr,
                *Wo = nullptr, *bo = nullptr;
    for (int i = 0; i < n_in; i++) {
        switch (in_sizes[i]) {
            case 4259840: x  = (const float*)d_in[i]; break;  // (4,4160,256)
            case 1048576: wm = (const float*)d_in[i]; break;  // (4,64,4096)
            case  196608: Wq = (const float*)d_in[i]; break;  // (256,768)
            case     768: bq = (const float*)d_in[i]; break;
            case   65536: Wo = (const float*)d_in[i]; break;  // (256,256)
            case     256: bo = (const float*)d_in[i]; break;
            default: break;
        }
    }

    // 1) qkv = x @ W_qkv + b_qkv   (M=16640, N=768, K=256) — tf32 tensor cores
    k_qkv<<<dim3(768 / 128, (CB * CTT) / 128), 256>>>(x, Wq, bq);
    // 2) expa = wm^T @ x_words      (per batch: 4096 x 256, K=64) — fp32
    k_expa<<<dim3(CE / 64, CF / 64, CB), 256>>>(wm, x);
    // 3) word-token passthrough rows
    k_copy<<<256, 256>>>(x);
    // 4) local + word-token attention
    k_attn<<<dim3(CF / 64, CB * CH), 256>>>();
    // 5) out = attn @ W_out + b_out (M=16640, N=256, K=256) — tf32 tensor cores
    k_out<<<dim3(256 / 128, (CB * CTT) / 128), 256>>>(Wo, bo, (float*)d_out);
}